// round 6
// baseline (speedup 1.0000x reference)
#include <cuda_runtime.h>
#include <cstdint>

// x: (8, 256, 256, 32) fp32, reflect-pad 3x3 patch extraction.
// out[b,h,w, c*9 + i] = x[b, reflect(h + i/3 - 1), reflect(w + i%3 - 1), c]
//
// Warp = 2-pixel strip along W (2.3KB smem/warp -> 64 warps/SM = 100% occ):
//   - 12 coalesced 128B line loads (3 rows x 4 cols, lane = channel)
//   - register->smem scatter into final output order (stride-9 word scatter
//     is a permutation mod 32 banks -> conflict-free)
//   - CTA covers 32 contiguous pixels = 36864 contiguous output bytes:
//     ONE cp.async.bulk (TMA) smem->gmem burst per CTA after __syncthreads.

static constexpr int B = 8;
static constexpr int H = 256;
static constexpr int W = 256;
static constexpr int C = 32;
static constexpr int TAPS = 9;
static constexpr int OUT_PER_PIX = C * TAPS;            // 288 floats = 1152 B
static constexpr int PIX_PER_WARP = 2;
static constexpr int WARPS_PER_BLOCK = 16;
static constexpr int THREADS = WARPS_PER_BLOCK * 32;    // 512
static constexpr int PIX_PER_BLOCK = PIX_PER_WARP * WARPS_PER_BLOCK;   // 32
static constexpr int BYTES_PER_BLOCK = PIX_PER_BLOCK * OUT_PER_PIX * 4; // 36864

__device__ __forceinline__ uint32_t smem_u32(const void* p) {
    uint32_t a;
    asm("{ .reg .u64 t; cvta.to.shared.u64 t, %1; cvt.u32.u64 %0, t; }"
        : "=r"(a) : "l"(p));
    return a;
}

__global__ __launch_bounds__(THREADS)
void patch_extract_kernel(const float* __restrict__ x, float* __restrict__ out) {
    const int warp = threadIdx.x >> 5;
    const int lane = threadIdx.x & 31;

    // blockIdx.y = b*H + h (2048 rows); blockIdx.x = 32-pixel group (8 per row)
    const int h = blockIdx.y & (H - 1);
    const int b = blockIdx.y >> 8;
    const int w0 = (blockIdx.x * WARPS_PER_BLOCK + warp) * PIX_PER_WARP;

    // Staging in final output order; warp-order == pixel-order, so the whole
    // CTA slab is the 36864B contiguous gmem block for its 32 pixels.
    __shared__ __align__(16) float sm[WARPS_PER_BLOCK][PIX_PER_WARP * OUT_PER_PIX];
    float* s = sm[warp];

    // Reflected rows (3) and columns (4: w0-1 .. w0+2). PAD=1: -1 -> 1, N -> N-2.
    int rh[3];
#pragma unroll
    for (int d = 0; d < 3; d++) {
        int r = h + d - 1;
        rh[d] = (r < 0) ? 1 : ((r >= H) ? H - 2 : r);
    }
    int rw[4];
#pragma unroll
    for (int t = 0; t < 4; t++) {
        int cc = w0 - 1 + t;
        rw[t] = (cc < 0) ? 1 : ((cc >= W) ? W - 2 : cc);
    }

    const float* xb = x + (size_t)b * H * W * C;

    // 12 independent, fully-coalesced 128B line loads (lane = channel).
    float v[3][4];
#pragma unroll
    for (int dr = 0; dr < 3; dr++) {
        const float* rp = xb + (size_t)rh[dr] * W * C + lane;
#pragma unroll
        for (int t = 0; t < 4; t++) {
            v[dr][t] = rp[rw[t] * C];
        }
    }

    // Scatter in output order: s[p*288 + c*9 + (dr*3+dj)] = v[dr][p+dj].
    const int lb = lane * TAPS;
#pragma unroll
    for (int p = 0; p < PIX_PER_WARP; p++) {
#pragma unroll
        for (int dr = 0; dr < 3; dr++) {
#pragma unroll
            for (int dj = 0; dj < 3; dj++) {
                s[p * OUT_PER_PIX + lb + dr * 3 + dj] = v[dr][p + dj];
            }
        }
    }
    __syncthreads();

    // One TMA bulk burst per CTA: 36864B smem (final order) -> gmem.
    if (threadIdx.x == 0) {
        const size_t pix0 = (size_t)blockIdx.y * W + (size_t)blockIdx.x * PIX_PER_BLOCK;
        float* gdst = out + pix0 * OUT_PER_PIX;
        const uint32_t saddr = smem_u32(&sm[0][0]);
        asm volatile("fence.proxy.async.shared::cta;" ::: "memory");
        asm volatile(
            "cp.async.bulk.global.shared::cta.bulk_group [%0], [%1], %2;"
            :: "l"(gdst), "r"(saddr), "r"((uint32_t)BYTES_PER_BLOCK)
            : "memory");
        asm volatile("cp.async.bulk.commit_group;" ::: "memory");
        // smem must stay live until the bulk copy's smem reads complete.
        asm volatile("cp.async.bulk.wait_group 0;" ::: "memory");
    }
    __syncthreads();
}

extern "C" void kernel_launch(void* const* d_in, const int* in_sizes, int n_in,
                              void* d_out, int out_size) {
    const float* x = (const float*)d_in[0];
    float* out = (float*)d_out;
    (void)in_sizes; (void)n_in; (void)out_size;

    dim3 grid(W / PIX_PER_BLOCK, B * H);   // (8, 2048)
    patch_extract_kernel<<<grid, THREADS>>>(x, out);
}

// round 7
// speedup vs baseline: 1.0171x; 1.0171x over previous
#include <cuda_runtime.h>
#include <cstdint>

// x: (8, 256, 256, 32) fp32, reflect-pad 3x3 patch extraction.
// out[b,h,w, c*9 + i] = x[b, reflect(h + i/3 - 1), reflect(w + i%3 - 1), c]
//
// Warp = 4-pixel strip along W (best-measured config):
//   - 18 coalesced 128B line loads (3 rows x 6 cols, lane = channel)
//   - register->smem scatter into final output order (stride-9 word scatter
//     is a permutation mod 32 banks -> conflict-free)
//   - half-CTA (4 warps = 16 pixels = 18432B contiguous) synchronizes on a
//     named barrier, then ONE elected thread issues a single cp.async.bulk
//     (TMA) smem->gmem burst for that half. 2 bursts/CTA, draining
//     independently.

static constexpr int B = 8;
static constexpr int H = 256;
static constexpr int W = 256;
static constexpr int C = 32;
static constexpr int TAPS = 9;
static constexpr int OUT_PER_PIX = C * TAPS;             // 288 floats = 1152 B
static constexpr int PIX_PER_WARP = 4;
static constexpr int WARPS_PER_BLOCK = 8;
static constexpr int THREADS = WARPS_PER_BLOCK * 32;     // 256
static constexpr int PIX_PER_BLOCK = PIX_PER_WARP * WARPS_PER_BLOCK;   // 32
static constexpr int PIX_PER_HALF = PIX_PER_BLOCK / 2;                 // 16
static constexpr int BYTES_PER_HALF = PIX_PER_HALF * OUT_PER_PIX * 4;  // 18432

__device__ __forceinline__ uint32_t smem_u32(const void* p) {
    uint32_t a;
    asm("{ .reg .u64 t; cvta.to.shared.u64 t, %1; cvt.u32.u64 %0, t; }"
        : "=r"(a) : "l"(p));
    return a;
}

__global__ __launch_bounds__(THREADS)
void patch_extract_kernel(const float* __restrict__ x, float* __restrict__ out) {
    const int warp = threadIdx.x >> 5;
    const int lane = threadIdx.x & 31;

    // blockIdx.y = b*H + h (2048 rows); blockIdx.x = 32-pixel group (8 per row)
    const int h = blockIdx.y & (H - 1);
    const int b = blockIdx.y >> 8;
    const int w0 = (blockIdx.x * WARPS_PER_BLOCK + warp) * PIX_PER_WARP;

    // Staging in final output order; warp-order == pixel-order, so each
    // 4-warp half is an 18432B contiguous gmem block.
    __shared__ __align__(16) float sm[WARPS_PER_BLOCK][PIX_PER_WARP * OUT_PER_PIX];
    float* s = sm[warp];

    // Reflected rows (3) and columns (6: w0-1 .. w0+4). PAD=1: -1 -> 1, N -> N-2.
    int rh[3];
#pragma unroll
    for (int d = 0; d < 3; d++) {
        int r = h + d - 1;
        rh[d] = (r < 0) ? 1 : ((r >= H) ? H - 2 : r);
    }
    int rw[6];
#pragma unroll
    for (int t = 0; t < 6; t++) {
        int cc = w0 - 1 + t;
        rw[t] = (cc < 0) ? 1 : ((cc >= W) ? W - 2 : cc);
    }

    const float* xb = x + (size_t)b * H * W * C;

    // 18 independent, fully-coalesced 128B line loads (lane = channel).
    float v[3][6];
#pragma unroll
    for (int dr = 0; dr < 3; dr++) {
        const float* rp = xb + (size_t)rh[dr] * W * C + lane;
#pragma unroll
        for (int t = 0; t < 6; t++) {
            v[dr][t] = rp[rw[t] * C];
        }
    }

    // Scatter in output order: s[p*288 + c*9 + (dr*3+dj)] = v[dr][p+dj].
    const int lb = lane * TAPS;
#pragma unroll
    for (int p = 0; p < PIX_PER_WARP; p++) {
#pragma unroll
        for (int dr = 0; dr < 3; dr++) {
#pragma unroll
            for (int dj = 0; dj < 3; dj++) {
                s[p * OUT_PER_PIX + lb + dr * 3 + dj] = v[dr][p + dj];
            }
        }
    }

    // Half-CTA sync (warps 0-3 -> barrier 1, warps 4-7 -> barrier 2), then one
    // TMA burst per half. bar.sync drains the half's pending STS.
    const int half = warp >> 2;
    asm volatile("bar.sync %0, 128;" :: "r"(half + 1) : "memory");

    if ((threadIdx.x & 127) == 0) {
        const size_t pix0 = (size_t)blockIdx.y * W
                          + (size_t)blockIdx.x * PIX_PER_BLOCK
                          + (size_t)half * PIX_PER_HALF;
        float* gdst = out + pix0 * OUT_PER_PIX;
        const uint32_t saddr = smem_u32(&sm[half * 4][0]);
        asm volatile("fence.proxy.async.shared::cta;" ::: "memory");
        asm volatile(
            "cp.async.bulk.global.shared::cta.bulk_group [%0], [%1], %2;"
            :: "l"(gdst), "r"(saddr), "r"((uint32_t)BYTES_PER_HALF)
            : "memory");
        asm volatile("cp.async.bulk.commit_group;" ::: "memory");
        // smem must stay live until the bulk copy's smem reads complete.
        asm volatile("cp.async.bulk.wait_group 0;" ::: "memory");
    }
    // No thread may exit (deallocating smem) before both bursts have drained.
    __syncthreads();
}

extern "C" void kernel_launch(void* const* d_in, const int* in_sizes, int n_in,
                              void* d_out, int out_size) {
    const float* x = (const float*)d_in[0];
    float* out = (float*)d_out;
    (void)in_sizes; (void)n_in; (void)out_size;

    dim3 grid(W / PIX_PER_BLOCK, B * H);   // (8, 2048)
    patch_extract_kernel<<<grid, THREADS>>>(x, out);
}